// round 3
// baseline (speedup 1.0000x reference)
#include <cuda_runtime.h>
#include <math.h>

#define B_    4
#define N_    4096
#define K_    24
#define CIN_  64
#define COUT_ 128
#define BN_TOT (B_*N_)            // 16384
#define M_TOT  (BN_TOT*K_)        // 393216
#define EPS_  1e-5f

// ---------------- scratch (static device memory; no allocs) ----------------
__device__ float g_xT[BN_TOT*CIN_];                   // [b][n][c]
__device__ int   g_idx[M_TOT];                        // [b][n][k]
__device__ float g_D[(size_t)M_TOT*CIN_];             // raw diff  [m][c]
__device__ float g_anchor[BN_TOT*COUT_];              // pts @ Wp^T
__device__ float g_T[(size_t)M_TOT*COUT_];            // transfer conv raw out
__device__ float g_U[(size_t)M_TOT*COUT_];            // block0 conv1 raw out
__device__ float g_V[(size_t)M_TOT*COUT_];            // block0 conv2 raw out
__device__ float g_Z [BN_TOT*COUT_];                  // pooled
__device__ float g_Z1[BN_TOT*COUT_];
__device__ float g_Z2[BN_TOT*COUT_];
__device__ float g_Wa[COUT_*CIN_];                    // wt[:, :64] * alpha
__device__ float g_Wp[COUT_*CIN_];                    // wt[:, 64:]
__device__ float g_const1[COUT_];                     // bt + wt[:, :64] @ beta
__device__ float g_ssum[5*128];                       // BN sums per stage
__device__ float g_ssq [5*128];
__device__ float g_coef[5*256];                       // per stage: a[128], c[128]
__device__ float g_bsum[B_];
__device__ float g_bsq [B_];
__device__ float g_invstd[B_];

// ---------------- small utility kernels ----------------
__global__ void zero_stats_kernel() {
    int i = threadIdx.x;              // 640 threads
    g_ssum[i] = 0.f; g_ssq[i] = 0.f;
    if (i < B_) { g_bsum[i] = 0.f; g_bsq[i] = 0.f; }
}

__global__ void transpose_x_kernel(const float* __restrict__ x) {
    __shared__ float tile[32][33];
    int b = blockIdx.z;
    int n0 = blockIdx.x * 32, c0 = blockIdx.y * 32;
    int tx = threadIdx.x, ty = threadIdx.y;
    #pragma unroll
    for (int rr = 0; rr < 4; ++rr) {
        int c = c0 + ty + rr*8;
        tile[ty + rr*8][tx] = x[((size_t)b*CIN_ + c)*N_ + n0 + tx];
    }
    __syncthreads();
    #pragma unroll
    for (int rr = 0; rr < 4; ++rr) {
        int n = n0 + ty + rr*8;
        g_xT[((size_t)b*N_ + n)*CIN_ + c0 + tx] = tile[tx][ty + rr*8];
    }
}

__global__ void prep_kernel(const float* __restrict__ wt,
                            const float* __restrict__ alpha,
                            const float* __restrict__ beta,
                            const float* __restrict__ bt) {
    int t = blockIdx.x * blockDim.x + threadIdx.x;
    if (t < COUT_*CIN_) {
        int o = t >> 6, c = t & 63;
        g_Wa[t] = wt[o*128 + c] * alpha[c];
        g_Wp[t] = wt[o*128 + 64 + c];
    }
    if (t < COUT_) {
        float s = bt[t];
        #pragma unroll 8
        for (int c = 0; c < CIN_; ++c) s += wt[t*128 + c] * beta[c];
        g_const1[t] = s;
    }
}

// ---------------- kNN: brute force, top-24 per query ----------------
__global__ void knn_kernel(const float* __restrict__ xyz) {
    extern __shared__ float s[];
    float* sx = s;
    float* sy = s + N_;
    float* sz = s + 2*N_;
    float* sq = s + 3*N_;
    int b = blockIdx.y;
    const float* xb = xyz + (size_t)b*3*N_;
    for (int i = threadIdx.x; i < N_; i += blockDim.x) {
        float X = xb[i], Y = xb[N_ + i], Z = xb[2*N_ + i];
        sx[i] = X; sy[i] = Y; sz[i] = Z;
        sq[i] = X*X + Y*Y + Z*Z;
    }
    __syncthreads();
    int q = blockIdx.x * blockDim.x + threadIdx.x;
    float qx = sx[q], qy = sy[q], qz = sz[q], qs = sq[q];
    float kd[K_]; int ki[K_];
    #pragma unroll
    for (int t = 0; t < K_; ++t) { kd[t] = 3.4e38f; ki[t] = 0; }
    float worst = 3.4e38f;
    for (int j = 0; j < N_; ++j) {
        float d = qs + sq[j] - 2.f*(qx*sx[j] + qy*sy[j] + qz*sz[j]);
        if (d < worst) {
            int p = K_ - 1;
            while (p > 0 && kd[p-1] > d) { kd[p] = kd[p-1]; ki[p] = ki[p-1]; --p; }
            kd[p] = d; ki[p] = j;
            worst = kd[K_-1];
        }
    }
    int* o = g_idx + ((size_t)b*N_ + q)*K_;
    #pragma unroll
    for (int t = 0; t < K_; ++t) o[t] = ki[t];
}

// ---------------- gather + diff + per-batch std stats ----------------
__global__ void gather_diff_kernel() {
    __shared__ float bs[8], bs2[8];
    int wid = threadIdx.x >> 5, lane = threadIdx.x & 31;
    int m = blockIdx.x * 8 + wid;                       // 8 warps, one m each
    int b = m / (N_*K_);
    int nk = m - b*(N_*K_);
    int n = nk / K_;
    int j = g_idx[m];
    const float2* src = reinterpret_cast<const float2*>(g_xT + ((size_t)b*N_ + j)*CIN_);
    const float2* anc = reinterpret_cast<const float2*>(g_xT + ((size_t)b*N_ + n)*CIN_);
    float2 gv = src[lane];
    float2 pv = anc[lane];
    float2 dv = make_float2(gv.x - pv.x, gv.y - pv.y);
    reinterpret_cast<float2*>(g_D + (size_t)m*CIN_)[lane] = dv;
    float s  = dv.x + dv.y;
    float s2 = dv.x*dv.x + dv.y*dv.y;
    #pragma unroll
    for (int off = 16; off; off >>= 1) {
        s  += __shfl_xor_sync(0xffffffffu, s,  off);
        s2 += __shfl_xor_sync(0xffffffffu, s2, off);
    }
    if (lane == 0) { bs[wid] = s; bs2[wid] = s2; }
    __syncthreads();
    if (threadIdx.x == 0) {
        float S = 0.f, S2 = 0.f;
        #pragma unroll
        for (int i = 0; i < 8; ++i) { S += bs[i]; S2 += bs2[i]; }
        atomicAdd(&g_bsum[b], S);
        atomicAdd(&g_bsq[b],  S2);
    }
}

__global__ void std_fin_kernel() {
    int b = threadIdx.x;
    if (b < B_) {
        const float cnt = (float)(N_*K_*CIN_);          // 6291456
        float mean = g_bsum[b] / cnt;
        float var  = (g_bsq[b] - cnt*mean*mean) / (cnt - 1.f);
        var = fmaxf(var, 0.f);
        g_invstd[b] = 1.f / (sqrtf(var) + EPS_);
    }
}

// ---------------- generic fused GEMM ----------------
// C[m, o] = (pre(A[m,:]) @ W[o,:]^T) (+ epilogue), 128x128 tile, full-K in smem.
// PRE:  A-load applies per-column affine+relu (BN of previous stage).
// G1:   epilogue: acc*invstd[batch] + anchor[m/K][o] + const1[o].
// bias: epilogue add; stats: per-channel sum/sumsq atomics for BN.
template<int KDIM, bool PRE, bool G1>
__global__ __launch_bounds__(256)
void gemm_kernel(const float* __restrict__ A,
                 const float* __restrict__ W,
                 float* __restrict__ Cmat,
                 const float* __restrict__ preA,
                 const float* __restrict__ preC,
                 const float* __restrict__ bias,
                 const float* __restrict__ invstd,
                 const float* __restrict__ anchor,
                 const float* __restrict__ cnst,
                 float* __restrict__ stat_sum,
                 float* __restrict__ stat_sq) {
    constexpr int LDA = 132;
    extern __shared__ float sm[];
    float* As = sm;                  // KDIM * LDA
    float* Bs = sm + KDIM*LDA;       // KDIM * LDA
    const int tid = threadIdx.x;
    const int m0 = blockIdx.x * 128;

    for (int i = tid; i < 128*KDIM; i += 256) {
        int o = i / KDIM, k = i - o*KDIM;
        Bs[k*LDA + o] = W[i];
    }
    for (int i = tid; i < 128*KDIM; i += 256) {
        int r = i / KDIM, k = i - r*KDIM;
        float v = A[(size_t)(m0 + r)*KDIM + k];
        if (PRE) v = fmaxf(fmaf(preA[k], v, preC[k]), 0.f);
        As[k*LDA + r] = v;
    }
    __syncthreads();

    const int tx = tid & 15, ty = tid >> 4;
    float acc[8][8];
    #pragma unroll
    for (int i = 0; i < 8; ++i)
        #pragma unroll
        for (int jj = 0; jj < 8; ++jj) acc[i][jj] = 0.f;

    const float* ap = As + ty*8;
    const float* bp = Bs + tx*8;
    #pragma unroll 4
    for (int k = 0; k < KDIM; ++k) {
        float4 a0 = *reinterpret_cast<const float4*>(ap + k*LDA);
        float4 a1 = *reinterpret_cast<const float4*>(ap + k*LDA + 4);
        float4 b0 = *reinterpret_cast<const float4*>(bp + k*LDA);
        float4 b1 = *reinterpret_cast<const float4*>(bp + k*LDA + 4);
        float av[8] = {a0.x,a0.y,a0.z,a0.w,a1.x,a1.y,a1.z,a1.w};
        float bv[8] = {b0.x,b0.y,b0.z,b0.w,b1.x,b1.y,b1.z,b1.w};
        #pragma unroll
        for (int i = 0; i < 8; ++i)
            #pragma unroll
            for (int jj = 0; jj < 8; ++jj)
                acc[i][jj] = fmaf(av[i], bv[jj], acc[i][jj]);
    }

    if (G1) {
        const float inv = invstd[m0 / (N_*K_)];
        #pragma unroll
        for (int i = 0; i < 8; ++i) {
            int m = m0 + ty*8 + i;
            const float* anc = anchor + (size_t)(m / K_)*COUT_ + tx*8;
            #pragma unroll
            for (int jj = 0; jj < 8; ++jj)
                acc[i][jj] = fmaf(acc[i][jj], inv, anc[jj] + cnst[tx*8 + jj]);
        }
    } else if (bias != nullptr) {
        #pragma unroll
        for (int jj = 0; jj < 8; ++jj) {
            float bj = bias[tx*8 + jj];
            #pragma unroll
            for (int i = 0; i < 8; ++i) acc[i][jj] += bj;
        }
    }

    #pragma unroll
    for (int i = 0; i < 8; ++i) {
        float* cp = Cmat + (size_t)(m0 + ty*8 + i)*COUT_ + tx*8;
        *reinterpret_cast<float4*>(cp)     = make_float4(acc[i][0],acc[i][1],acc[i][2],acc[i][3]);
        *reinterpret_cast<float4*>(cp + 4) = make_float4(acc[i][4],acc[i][5],acc[i][6],acc[i][7]);
    }

    if (stat_sum != nullptr) {
        __syncthreads();
        float* ssum = sm;
        float* ssq  = sm + 128;
        if (tid < 128) { ssum[tid] = 0.f; ssq[tid] = 0.f; }
        __syncthreads();
        #pragma unroll
        for (int jj = 0; jj < 8; ++jj) {
            float s = 0.f, s2 = 0.f;
            #pragma unroll
            for (int i = 0; i < 8; ++i) { float v = acc[i][jj]; s += v; s2 = fmaf(v, v, s2); }
            atomicAdd(&ssum[tx*8 + jj], s);
            atomicAdd(&ssq [tx*8 + jj], s2);
        }
        __syncthreads();
        if (tid < 128) {
            atomicAdd(&stat_sum[tid], ssum[tid]);
            atomicAdd(&stat_sq [tid], ssq[tid]);
        }
    }
}

// ---------------- BN finalize: a = g/sqrt(var+eps), c = beta - mean*a -----
__global__ void bn_fin_kernel(int stage, float inv_cnt,
                              const float* __restrict__ gamma,
                              const float* __restrict__ betab) {
    int o = threadIdx.x;
    float mean = g_ssum[stage*128 + o] * inv_cnt;
    float var  = g_ssq [stage*128 + o] * inv_cnt - mean*mean;
    var = fmaxf(var, 0.f);
    float a = gamma[o] / sqrtf(var + EPS_);
    g_coef[stage*256 + o]       = a;
    g_coef[stage*256 + 128 + o] = betab[o] - mean*a;
}

// ---------------- residual + relu + max-pool over K ----------------
// Z[bn][o] = max_k relu( (a2*V + c2) + relu(a0*T + c0) )
__global__ void pool_kernel() {
    int bn = blockIdx.x;
    int o  = threadIdx.x;
    float A2 = g_coef[2*256 + o],       C2 = g_coef[2*256 + 128 + o];
    float A0 = g_coef[o],               C0 = g_coef[128 + o];
    const float* vp = g_V + (size_t)bn*K_*COUT_ + o;
    const float* tp = g_T + (size_t)bn*K_*COUT_ + o;
    float mx = -3.4e38f;
    #pragma unroll 8
    for (int k = 0; k < K_; ++k) {
        float v = fmaf(A2, vp[k*COUT_], C2) + fmaxf(fmaf(A0, tp[k*COUT_], C0), 0.f);
        mx = fmaxf(mx, fmaxf(v, 0.f));
    }
    g_Z[(size_t)bn*COUT_ + o] = mx;
}

// ---------------- final: BN + residual + relu + transpose to [B,C,N] ------
__global__ void out_kernel(float* __restrict__ out) {
    __shared__ float tile[32][33];
    int b = blockIdx.z;
    int n0 = blockIdx.x * 32, o0 = blockIdx.y * 32;
    int tx = threadIdx.x, ty = threadIdx.y;
    float a5 = g_coef[4*256 + o0 + tx];
    float c5 = g_coef[4*256 + 128 + o0 + tx];
    #pragma unroll
    for (int rr = 0; rr < 4; ++rr) {
        int n  = n0 + ty + rr*8;
        size_t bn = (size_t)b*N_ + n;
        float v = fmaf(a5, g_Z2[bn*COUT_ + o0 + tx], c5) + g_Z[bn*COUT_ + o0 + tx];
        tile[ty + rr*8][tx] = fmaxf(v, 0.f);
    }
    __syncthreads();
    #pragma unroll
    for (int rr = 0; rr < 4; ++rr) {
        int o = o0 + ty + rr*8;
        out[((size_t)b*COUT_ + o)*N_ + n0 + tx] = tile[tx][ty + rr*8];
    }
}

// ---------------- host ----------------
extern "C" void kernel_launch(void* const* d_in, const int* in_sizes, int n_in,
                              void* d_out, int out_size) {
    const float* x    = (const float*)d_in[0];
    const float* xyz  = (const float*)d_in[1];
    const float* alpha= (const float*)d_in[2];
    const float* beta = (const float*)d_in[3];
    const float* wt   = (const float*)d_in[4];
    const float* bt   = (const float*)d_in[5];
    const float* gt   = (const float*)d_in[6];
    const float* btt  = (const float*)d_in[7];
    const float* w01  = (const float*)d_in[8];
    const float* b01  = (const float*)d_in[9];
    const float* g01  = (const float*)d_in[10];
    const float* bb01 = (const float*)d_in[11];
    const float* w02  = (const float*)d_in[12];
    const float* b02  = (const float*)d_in[13];
    const float* g02  = (const float*)d_in[14];
    const float* bb02 = (const float*)d_in[15];
    const float* w11  = (const float*)d_in[16];
    const float* b11  = (const float*)d_in[17];
    const float* g11  = (const float*)d_in[18];
    const float* bb11 = (const float*)d_in[19];
    const float* w12  = (const float*)d_in[20];
    const float* b12  = (const float*)d_in[21];
    const float* g12  = (const float*)d_in[22];
    const float* bb12 = (const float*)d_in[23];
    float* out = (float*)d_out;

    float *pXT, *pD, *pAnch, *pT, *pU, *pV, *pZ, *pZ1, *pZ2;
    float *pWa, *pWp, *pC1, *pSsum, *pSsq, *pCoef, *pInv;
    cudaGetSymbolAddress((void**)&pXT,   g_xT);
    cudaGetSymbolAddress((void**)&pD,    g_D);
    cudaGetSymbolAddress((void**)&pAnch, g_anchor);
    cudaGetSymbolAddress((void**)&pT,    g_T);
    cudaGetSymbolAddress((void**)&pU,    g_U);
    cudaGetSymbolAddress((void**)&pV,    g_V);
    cudaGetSymbolAddress((void**)&pZ,    g_Z);
    cudaGetSymbolAddress((void**)&pZ1,   g_Z1);
    cudaGetSymbolAddress((void**)&pZ2,   g_Z2);
    cudaGetSymbolAddress((void**)&pWa,   g_Wa);
    cudaGetSymbolAddress((void**)&pWp,   g_Wp);
    cudaGetSymbolAddress((void**)&pC1,   g_const1);
    cudaGetSymbolAddress((void**)&pSsum, g_ssum);
    cudaGetSymbolAddress((void**)&pSsq,  g_ssq);
    cudaGetSymbolAddress((void**)&pCoef, g_coef);
    cudaGetSymbolAddress((void**)&pInv,  g_invstd);

    const int smem64  = 2 * 64  * 132 * 4;   // 67584
    const int smem128 = 2 * 128 * 132 * 4;   // 135168
    cudaFuncSetAttribute(knn_kernel, cudaFuncAttributeMaxDynamicSharedMemorySize, 65536);
    cudaFuncSetAttribute(gemm_kernel<64,  false, false>, cudaFuncAttributeMaxDynamicSharedMemorySize, smem64);
    cudaFuncSetAttribute(gemm_kernel<64,  false, true >, cudaFuncAttributeMaxDynamicSharedMemorySize, smem64);
    cudaFuncSetAttribute(gemm_kernel<128, true,  false>, cudaFuncAttributeMaxDynamicSharedMemorySize, smem128);
    cudaFuncSetAttribute(gemm_kernel<128, false, false>, cudaFuncAttributeMaxDynamicSharedMemorySize, smem128);

    const float invM  = 1.f / (float)M_TOT;
    const float invBN = 1.f / (float)BN_TOT;

    zero_stats_kernel<<<1, 640>>>();
    transpose_x_kernel<<<dim3(N_/32, CIN_/32, B_), dim3(32, 8)>>>(x);
    knn_kernel<<<dim3(N_/128, B_), 128, 65536>>>(xyz);
    prep_kernel<<<32, 256>>>(wt, alpha, beta, bt);
    gather_diff_kernel<<<M_TOT/8, 256>>>();
    std_fin_kernel<<<1, 32>>>();

    // anchor = pts @ Wp^T
    gemm_kernel<64, false, false><<<BN_TOT/128, 256, smem64>>>(
        pXT, pWp, pAnch, nullptr, nullptr, nullptr,
        nullptr, nullptr, nullptr, nullptr, nullptr);

    // transfer conv: T = invstd*(D @ Wa^T) + anchor + const1   (stats stage 0)
    gemm_kernel<64, false, true><<<M_TOT/128, 256, smem64>>>(
        pD, pWa, pT, nullptr, nullptr, nullptr,
        pInv, pAnch, pC1, pSsum + 0, pSsq + 0);
    bn_fin_kernel<<<1, 128>>>(0, invM, gt, btt);

    // block0 conv1: U = W01 @ relu(bn0(T)) + b01   (stats stage 1)
    gemm_kernel<128, true, false><<<M_TOT/128, 256, smem128>>>(
        pT, w01, pU, pCoef + 0, pCoef + 128, b01,
        nullptr, nullptr, nullptr, pSsum + 128, pSsq + 128);
    bn_fin_kernel<<<1, 128>>>(1, invM, g01, bb01);

    // block0 conv2: V = W02 @ relu(bn1(U)) + b02   (stats stage 2)
    gemm_kernel<128, true, false><<<M_TOT/128, 256, smem128>>>(
        pU, w02, pV, pCoef + 256, pCoef + 384, b02,
        nullptr, nullptr, nullptr, pSsum + 256, pSsq + 256);
    bn_fin_kernel<<<1, 128>>>(2, invM, g02, bb02);

    // residual + relu + maxpool over K
    pool_kernel<<<BN_TOT, 128>>>();

    // block1 conv1: Z1 = W11 @ Z + b11   (stats stage 3)
    gemm_kernel<128, false, false><<<BN_TOT/128, 256, smem128>>>(
        pZ, w11, pZ1, nullptr, nullptr, b11,
        nullptr, nullptr, nullptr, pSsum + 384, pSsq + 384);
    bn_fin_kernel<<<1, 128>>>(3, invBN, g11, bb11);

    // block1 conv2: Z2 = W12 @ relu(bn3(Z1)) + b12   (stats stage 4)
    gemm_kernel<128, true, false><<<BN_TOT/128, 256, smem128>>>(
        pZ1, w12, pZ2, pCoef + 3*256, pCoef + 3*256 + 128, b12,
        nullptr, nullptr, nullptr, pSsum + 512, pSsq + 512);
    bn_fin_kernel<<<1, 128>>>(4, invBN, g12, bb12);

    // final: relu(bn4(Z2) + Z), transpose to [B, COUT, N]
    out_kernel<<<dim3(N_/32, COUT_/32, B_), dim3(32, 8)>>>(out);
}